// round 9
// baseline (speedup 1.0000x reference)
#include <cuda_runtime.h>
#include <cuda_bf16.h>
#include <mma.h>
#include <math.h>

using namespace nvcuda;

#define NN 8192
#define ELLW 320
#define KP1 800   // K=784 padded to multiple of 32

// padded smem strides (bank-conflict-free LDSM)
#define LDA_S 40   // A tile row stride in bf16 (80B)
#define LDB_S 72   // B tile row stride in bf16 (144B)

// ---------------- scratch (device globals; no allocation allowed) ----------
__device__ float g_d[NN];
__device__ int   g_cnt[NN];
__device__ int   g_colidx[NN * ELLW];
__device__ float g_H0s[NN * 256];
__device__ float g_X1s[NN * 256];
__device__ float g_ZS[NN * 384];
__device__ float g_S1 [NN * 256];
__device__ float g_S1s[NN * 256];
__device__ float g_U [NN * 256];
__device__ float g_Wcat [256 * 384];
__device__ float g_bcat [384];
__device__ float g_xp1[256 * 128];
__device__ float g_A2 [256 * 256];
__device__ float g_T  [256 * 256];
__device__ float g_X2 [256 * 128];
__device__ float g_ZS2[256 * 192];
__device__ float g_S2 [256 * 64];
__device__ float g_V2 [256 * 64];
__device__ float g_xp2[64 * 128];
__device__ float g_A3 [64 * 64];
__device__ float g_X3 [64 * 128];
__device__ float g_Z3 [64 * 128];
__device__ float g_ca3[64];

// grid-barrier state (self-resetting arrive counter, monotonic phase)
__device__ unsigned long long g_phase_ctr;
__device__ unsigned int g_arrive_ctr;

// bf16 hi/lo split buffers
__device__ __align__(16) __nv_bfloat16 g_xhi[NN * KP1];
__device__ __align__(16) __nv_bfloat16 g_xlo[NN * KP1];
__device__ __align__(16) __nv_bfloat16 g_w1hi[KP1 * 256];
__device__ __align__(16) __nv_bfloat16 g_w1lo[KP1 * 256];
__device__ __align__(16) __nv_bfloat16 g_Yhi[NN * 256];
__device__ __align__(16) __nv_bfloat16 g_Ylo[NN * 256];
__device__ __align__(16) __nv_bfloat16 g_wchi[256 * 384];
__device__ __align__(16) __nv_bfloat16 g_wclo[256 * 384];

// ---------------- one-pass ELL build + degrees ------------------------------
__global__ void ell_build(const float* __restrict__ adj, int* __restrict__ colidx,
                          int* __restrict__ cnt, float* __restrict__ drs) {
    int row = blockIdx.x;
    int tid = threadIdx.x, lane = tid & 31, w = tid >> 5;
    const float* ar = adj + (size_t)row * NN;
    __shared__ int woff[9];
    int base = w * 1024;
    unsigned msk = 0;
#pragma unroll
    for (int s = 0; s < 32; s++) {
        float v = ar[base + s * 32 + lane];
        msk |= (v != 0.f) ? (1u << s) : 0u;
    }
    int c = __popc(msk);
    for (int o = 16; o > 0; o >>= 1) c += __shfl_down_sync(0xffffffffu, c, o);
    if (lane == 0) woff[w + 1] = c;
    __syncthreads();
    if (tid == 0) {
        woff[0] = 0;
        for (int i = 1; i <= 8; i++) woff[i] += woff[i - 1];
    }
    __syncthreads();
    int off = woff[w];
    unsigned ltmask = (1u << lane) - 1u;
    int* ci = colidx + (size_t)row * ELLW;
#pragma unroll
    for (int s = 0; s < 32; s++) {
        unsigned bit = (msk >> s) & 1u;
        unsigned m = __ballot_sync(0xffffffffu, bit);
        if (bit) {
            int pos = off + __popc(m & ltmask);
            if (pos < ELLW) ci[pos] = base + s * 32 + lane;
        }
        off += __popc(m);
    }
    if (tid == 0) {
        int tot = woff[8];
        cnt[row] = tot;
        drs[row] = rsqrtf((float)tot);
    }
}

// ---------------- bf16 split conversions ------------------------------------
__global__ void cvt_split4(const float4* __restrict__ in,
                           __nv_bfloat162* __restrict__ hi,
                           __nv_bfloat162* __restrict__ lo, int n4) {
    int i = blockIdx.x * blockDim.x + threadIdx.x;
    if (i >= n4) return;
    float4 v = in[i];
    __nv_bfloat16 h0 = __float2bfloat16(v.x);
    __nv_bfloat16 h1 = __float2bfloat16(v.y);
    __nv_bfloat16 h2 = __float2bfloat16(v.z);
    __nv_bfloat16 h3 = __float2bfloat16(v.w);
    __nv_bfloat16 l0 = __float2bfloat16(v.x - __bfloat162float(h0));
    __nv_bfloat16 l1 = __float2bfloat16(v.y - __bfloat162float(h1));
    __nv_bfloat16 l2 = __float2bfloat16(v.z - __bfloat162float(h2));
    __nv_bfloat16 l3 = __float2bfloat16(v.w - __bfloat162float(h3));
    hi[2 * i]     = __nv_bfloat162(h0, h1);
    hi[2 * i + 1] = __nv_bfloat162(h2, h3);
    lo[2 * i]     = __nv_bfloat162(l0, l1);
    lo[2 * i + 1] = __nv_bfloat162(l2, l3);
}

__global__ void cvt_pad_cols(const float* __restrict__ in,
                             __nv_bfloat16* __restrict__ hi,
                             __nv_bfloat16* __restrict__ lo,
                             int M, int K, int KPp) {
    int idx = blockIdx.x * blockDim.x + threadIdx.x;
    if (idx >= M * KPp) return;
    int r = idx / KPp, c = idx - r * KPp;
    float v = (c < K) ? in[(size_t)r * K + c] : 0.f;
    __nv_bfloat16 h = __float2bfloat16(v);
    hi[idx] = h;
    lo[idx] = __float2bfloat16(v - __bfloat162float(h));
}

__global__ void cvt_pad_rows(const float* __restrict__ in,
                             __nv_bfloat16* __restrict__ hi,
                             __nv_bfloat16* __restrict__ lo,
                             int K, int KPp, int N) {
    int idx = blockIdx.x * blockDim.x + threadIdx.x;
    if (idx >= KPp * N) return;
    int r = idx / N;
    float v = (r < K) ? in[idx] : 0.f;
    __nv_bfloat16 h = __float2bfloat16(v);
    hi[idx] = h;
    lo[idx] = __float2bfloat16(v - __bfloat162float(h));
}

// ---------------- tensor GEMM: 64x64 tile, padded smem, 2-stage cp.async ---
__device__ __forceinline__ void cp16(void* sp, const void* gp) {
    unsigned a = (unsigned)__cvta_generic_to_shared(sp);
    asm volatile("cp.async.cg.shared.global [%0], [%1], 16;\n" :: "r"(a), "l"(gp));
}

#define STG_STRIDE 19456

__global__ __launch_bounds__(128) void wgemm3(const __nv_bfloat16* __restrict__ Ahi,
                                              const __nv_bfloat16* __restrict__ Alo,
                                              const __nv_bfloat16* __restrict__ Bhi,
                                              const __nv_bfloat16* __restrict__ Blo,
                                              float* __restrict__ C,
                                              int M, int N, int KPk,
                                              const float* __restrict__ bias,
                                              const float* __restrict__ rowscale) {
    __shared__ __align__(16) char smem[2 * STG_STRIDE];
    int tid = threadIdx.x;
    int wid = tid >> 5, lane = tid & 31;
    int wm = wid & 1, wn = wid >> 1;
    int bm = blockIdx.y * 64, bn = blockIdx.x * 64;

    wmma::fragment<wmma::accumulator, 16, 16, 16, float> acc[2][2];
#pragma unroll
    for (int i = 0; i < 2; i++)
#pragma unroll
        for (int j = 0; j < 2; j++) wmma::fill_fragment(acc[i][j], 0.f);

    int a_r = tid >> 2, a_c = (tid & 3) * 8;
    int b_r = tid >> 3, b_c = (tid & 7) * 8;

    int nk = KPk >> 5;
    auto sAhi = [&](int s) { return (__nv_bfloat16*)(smem + s * STG_STRIDE); };
    auto sAlo = [&](int s) { return (__nv_bfloat16*)(smem + s * STG_STRIDE + 5120); };
    auto sBhi = [&](int s) { return (__nv_bfloat16*)(smem + s * STG_STRIDE + 10240); };
    auto sBlo = [&](int s) { return (__nv_bfloat16*)(smem + s * STG_STRIDE + 14848); };

    auto load_stage = [&](int s, int k0) {
        __nv_bfloat16* ah = sAhi(s); __nv_bfloat16* al = sAlo(s);
        __nv_bfloat16* bh = sBhi(s); __nv_bfloat16* bl = sBlo(s);
#pragma unroll
        for (int i = 0; i < 2; i++) {
            int r = a_r + i * 32;
            cp16(&ah[r * LDA_S + a_c], &Ahi[(size_t)(bm + r) * KPk + k0 + a_c]);
            cp16(&al[r * LDA_S + a_c], &Alo[(size_t)(bm + r) * KPk + k0 + a_c]);
        }
#pragma unroll
        for (int i = 0; i < 2; i++) {
            int r = b_r + i * 16;
            cp16(&bh[r * LDB_S + b_c], &Bhi[(size_t)(k0 + r) * N + bn + b_c]);
            cp16(&bl[r * LDB_S + b_c], &Blo[(size_t)(k0 + r) * N + bn + b_c]);
        }
        asm volatile("cp.async.commit_group;\n");
    };

    load_stage(0, 0);
    for (int it = 0; it < nk; it++) {
        if (it + 1 < nk) {
            load_stage((it + 1) & 1, (it + 1) * 32);
            asm volatile("cp.async.wait_group 1;\n");
        } else {
            asm volatile("cp.async.wait_group 0;\n");
        }
        __syncthreads();
        int s = it & 1;
        __nv_bfloat16* ah_ = sAhi(s); __nv_bfloat16* al_ = sAlo(s);
        __nv_bfloat16* bh_ = sBhi(s); __nv_bfloat16* bl_ = sBlo(s);
#pragma unroll
        for (int ks = 0; ks < 2; ks++) {
            wmma::fragment<wmma::matrix_b, 16, 16, 16, __nv_bfloat16, wmma::row_major> bh[2], bl[2];
#pragma unroll
            for (int j = 0; j < 2; j++) {
                wmma::load_matrix_sync(bh[j], bh_ + (ks * 16) * LDB_S + wn * 32 + j * 16, LDB_S);
                wmma::load_matrix_sync(bl[j], bl_ + (ks * 16) * LDB_S + wn * 32 + j * 16, LDB_S);
            }
#pragma unroll
            for (int i = 0; i < 2; i++) {
                wmma::fragment<wmma::matrix_a, 16, 16, 16, __nv_bfloat16, wmma::row_major> ah, al;
                wmma::load_matrix_sync(ah, ah_ + (wm * 32 + i * 16) * LDA_S + ks * 16, LDA_S);
                wmma::load_matrix_sync(al, al_ + (wm * 32 + i * 16) * LDA_S + ks * 16, LDA_S);
#pragma unroll
                for (int j = 0; j < 2; j++) {
                    wmma::mma_sync(acc[i][j], ah, bh[j], acc[i][j]);
                    wmma::mma_sync(acc[i][j], ah, bl[j], acc[i][j]);
                    wmma::mma_sync(acc[i][j], al, bh[j], acc[i][j]);
                }
            }
        }
        __syncthreads();
    }

    float* myout = (float*)smem + wid * (32 * 36);
#pragma unroll
    for (int i = 0; i < 2; i++)
#pragma unroll
        for (int j = 0; j < 2; j++)
            wmma::store_matrix_sync(myout + i * 16 * 36 + j * 16, acc[i][j], 36,
                                    wmma::mem_row_major);
    int colg = bn + wn * 32 + lane;
    float bb = bias ? bias[colg] : 0.f;
#pragma unroll 4
    for (int rr = 0; rr < 32; rr++) {
        int rowg = bm + wm * 32 + rr;
        float sc = rowscale ? rowscale[rowg] : 1.f;
        C[(size_t)rowg * N + colg] = sc * (myout[rr * 36 + lane] + bb);
    }
}

// ---------------- SpMM ------------------------------------------------------
__global__ __launch_bounds__(256) void spmm4(const int* __restrict__ colidx,
                                             const int* __restrict__ cnt,
                                             const float* __restrict__ drs,
                                             const float4* __restrict__ B,
                                             float4* __restrict__ out,
                                             const float4* __restrict__ bias,
                                             __nv_bfloat162* __restrict__ outhi,
                                             __nv_bfloat162* __restrict__ outlo,
                                             int mode) {
    __shared__ int sidx[ELLW];
    __shared__ float4 sred[192];
    int row = blockIdx.x;
    int tid = threadIdx.x;
    int g = tid >> 6, c = tid & 63;
    int e = cnt[row];
    if (e > ELLW) e = ELLW;
    for (int i = tid; i < e; i += 256) sidx[i] = colidx[(size_t)row * ELLW + i];
    __syncthreads();

    float4 acc = make_float4(0.f, 0.f, 0.f, 0.f);
    int p = g;
    for (; p + 8 <= e; p += 8) {
        int j0 = sidx[p], j1 = sidx[p + 4];
        float4 v0 = B[(size_t)j0 * 64 + c];
        float4 v1 = B[(size_t)j1 * 64 + c];
        acc.x += v0.x; acc.y += v0.y; acc.z += v0.z; acc.w += v0.w;
        acc.x += v1.x; acc.y += v1.y; acc.z += v1.z; acc.w += v1.w;
    }
    for (; p < e; p += 4) {
        int j = sidx[p];
        float4 v = B[(size_t)j * 64 + c];
        acc.x += v.x; acc.y += v.y; acc.z += v.z; acc.w += v.w;
    }
    if (g > 0) sred[(g - 1) * 64 + c] = acc;
    __syncthreads();
    if (g == 0) {
        float4 a1 = sred[c], a2 = sred[64 + c], a3 = sred[128 + c];
        acc.x += a1.x + a2.x + a3.x;
        acc.y += a1.y + a2.y + a3.y;
        acc.z += a1.z + a2.z + a3.z;
        acc.w += a1.w + a2.w + a3.w;
        float s = drs[row];
        float4 r;
        if (mode == 1) {
            float4 b = bias[c];
            r.x = s * (s * acc.x + b.x);
            r.y = s * (s * acc.y + b.y);
            r.z = s * (s * acc.z + b.z);
            r.w = s * (s * acc.w + b.w);
        } else {
            r.x = s * acc.x; r.y = s * acc.y; r.z = s * acc.z; r.w = s * acc.w;
        }
        if (mode == 2) {
            __nv_bfloat16 h0 = __float2bfloat16(r.x);
            __nv_bfloat16 h1 = __float2bfloat16(r.y);
            __nv_bfloat16 h2 = __float2bfloat16(r.z);
            __nv_bfloat16 h3 = __float2bfloat16(r.w);
            outhi[(size_t)row * 128 + 2 * c]     = __nv_bfloat162(h0, h1);
            outhi[(size_t)row * 128 + 2 * c + 1] = __nv_bfloat162(h2, h3);
            outlo[(size_t)row * 128 + 2 * c] = __nv_bfloat162(
                __float2bfloat16(r.x - __bfloat162float(h0)),
                __float2bfloat16(r.y - __bfloat162float(h1)));
            outlo[(size_t)row * 128 + 2 * c + 1] = __nv_bfloat162(
                __float2bfloat16(r.z - __bfloat162float(h2)),
                __float2bfloat16(r.w - __bfloat162float(h3)));
        } else {
            out[(size_t)row * 64 + c] = r;
        }
    }
}

// ---------------- softmax (256 wide) with scaled+unscaled outputs ----------
__global__ void softmax_dual(const float* __restrict__ in, int ldi, int off,
                             const float* __restrict__ drs,
                             float* __restrict__ out, float* __restrict__ outs) {
    int row = blockIdx.x, t = threadIdx.x;
    __shared__ float sm[8];
    float v = in[(size_t)row * ldi + off + t];
    float m = v;
    for (int o = 16; o > 0; o >>= 1) m = fmaxf(m, __shfl_xor_sync(0xffffffffu, m, o));
    if ((t & 31) == 0) sm[t >> 5] = m;
    __syncthreads();
    if (t < 8) {
        float mm = sm[t];
        for (int o = 4; o > 0; o >>= 1) mm = fmaxf(mm, __shfl_xor_sync(0xffu, mm, o));
        sm[t] = mm;
    }
    __syncthreads();
    float mx = sm[0];
    __syncthreads();
    float e = expf(v - mx);
    float s = e;
    for (int o = 16; o > 0; o >>= 1) s += __shfl_xor_sync(0xffffffffu, s, o);
    if ((t & 31) == 0) sm[t >> 5] = s;
    __syncthreads();
    if (t < 8) {
        float ss = sm[t];
        for (int o = 4; o > 0; o >>= 1) ss += __shfl_xor_sync(0xffu, ss, o);
        sm[t] = ss;
    }
    __syncthreads();
    float r = e / sm[0];
    out[(size_t)row * 256 + t] = r;
    outs[(size_t)row * 256 + t] = drs[row] * r;
}

// ---------------- transpose GEMM: C += S^T @ V (32 rows/block) --------------
__global__ void tgemm_kernel(const float* __restrict__ S, int lds,
                             const float* __restrict__ V, int ldv,
                             float* __restrict__ C, int ldc, int K) {
    int ag = blockIdx.x * 32;
    int kchunk = K / gridDim.y;
    int k0 = blockIdx.y * kchunk, k1 = k0 + kchunk;
    int t = threadIdx.x;
    float acc[32];
#pragma unroll
    for (int u = 0; u < 32; u++) acc[u] = 0.f;
    for (int k = k0; k < k1; k++) {
        float v = V[(size_t)k * ldv + t];
        const float4* sp = (const float4*)(S + (size_t)k * lds + ag);
#pragma unroll
        for (int q = 0; q < 8; q++) {
            float4 s4 = sp[q];
            acc[q * 4 + 0] += s4.x * v;
            acc[q * 4 + 1] += s4.y * v;
            acc[q * 4 + 2] += s4.z * v;
            acc[q * 4 + 3] += s4.w * v;
        }
    }
#pragma unroll
    for (int u = 0; u < 32; u++) atomicAdd(&C[(ag + u) * ldc + t], acc[u]);
}

__global__ void zero2_kernel(float* a, int na, float* b, int nb) {
    int i = blockIdx.x * blockDim.x + threadIdx.x;
    if (i < na) a[i] = 0.f;
    else if (i < na + nb) b[i - na] = 0.f;
}

// ---------------- pack [W_d11 | W_d12] ---------------------------------------
__global__ void pack_wcat(const float* __restrict__ Wd11, const float* __restrict__ Wd12,
                          const float* __restrict__ bd11, const float* __restrict__ bd12,
                          float* __restrict__ Wcat, float* __restrict__ bcat) {
    int idx = blockIdx.x * blockDim.x + threadIdx.x;
    if (idx < 256 * 384) {
        int k = idx / 384, n = idx % 384;
        Wcat[idx] = (n < 128) ? Wd11[k * 128 + n] : Wd12[k * 256 + (n - 128)];
    }
    if (idx < 384) bcat[idx] = (idx < 128) ? bd11[idx] : bd12[idx - 128];
}

// ---------------- grid barrier (software, co-resident grid) -----------------
__device__ __forceinline__ void gbar(unsigned long long target) {
    __syncthreads();
    if (threadIdx.x == 0) {
        __threadfence();
        unsigned int old = atomicAdd(&g_arrive_ctr, 1u);
        if (old == gridDim.x - 1) {
            g_arrive_ctr = 0u;
            __threadfence();
            atomicAdd(&g_phase_ctr, 1ULL);
        } else {
            while (*(volatile unsigned long long*)&g_phase_ctr < target) { }
        }
        __threadfence();
    }
    __syncthreads();
}

// ---------------- fused level-2/3 tail (one launch, 10 grid barriers) -------
// grid = 256 blocks x 128 threads (all co-resident: ~600B smem, low regs)
__global__ __launch_bounds__(128) void tail_fused(
    const float* __restrict__ xp1, const float* __restrict__ A2,
    const float* __restrict__ Wg2, const float* __restrict__ bg2,
    const float* __restrict__ Wd21, const float* __restrict__ bd21,
    const float* __restrict__ Wd22, const float* __restrict__ bd22,
    const float* __restrict__ Wg3, const float* __restrict__ bg3,
    const float* __restrict__ Wd31, const float* __restrict__ bd31,
    const float* __restrict__ Wfc, const float* __restrict__ bfc,
    float* __restrict__ T, float* __restrict__ X2, float* __restrict__ ZS2,
    float* __restrict__ S2, float* __restrict__ V2, float* __restrict__ xp2,
    float* __restrict__ A3, float* __restrict__ X3, float* __restrict__ Z3,
    float* __restrict__ ca3, float* __restrict__ out) {
    int m = blockIdx.x, t = threadIdx.x;
    __shared__ float sh[132];
    __shared__ float logits[12];
    __shared__ float red;
    unsigned long long base = *(volatile unsigned long long*)&g_phase_ctr;

    // P0: T = xp1 @ Wg2   (256x128, K=128)
    {
        const float* a = xp1 + m * 128;
        float acc = 0.f;
#pragma unroll 8
        for (int k = 0; k < 128; k++) acc += a[k] * Wg2[k * 128 + t];
        T[m * 128 + t] = acc;
    }
    gbar(base + 1);
    // P1: X2 = A2 @ T + bg2   (K=256)
    {
        const float* a = A2 + m * 256;
        float acc = 0.f;
#pragma unroll 8
        for (int k = 0; k < 256; k++) acc += a[k] * T[k * 128 + t];
        X2[m * 128 + t] = acc + bg2[t];
    }
    gbar(base + 2);
    // P2: T(ld192) = X2 @ [Wd21 | Wd22]
    {
        const float* a = X2 + m * 128;
        float acc = 0.f;
#pragma unroll 8
        for (int k = 0; k < 128; k++) acc += a[k] * Wd21[k * 128 + t];
        T[m * 192 + t] = acc;
        if (t < 64) {
            float acc2 = 0.f;
#pragma unroll 8
            for (int k = 0; k < 128; k++) acc2 += a[k] * Wd22[k * 64 + t];
            T[m * 192 + 128 + t] = acc2;
        }
    }
    gbar(base + 3);
    // P3: ZS2 = A2 @ T(ld192) + bias   (K=256)
    {
        const float* a = A2 + m * 256;
        float acc = 0.f;
#pragma unroll 8
        for (int k = 0; k < 256; k++) acc += a[k] * T[k * 192 + t];
        ZS2[m * 192 + t] = acc + bd21[t];
        if (t < 64) {
            float acc2 = 0.f;
#pragma unroll 8
            for (int k = 0; k < 256; k++) acc2 += a[k] * T[k * 192 + 128 + t];
            ZS2[m * 192 + 128 + t] = acc2 + bd22[t];
        }
    }
    gbar(base + 4);
    // P4: S2 = softmax(ZS2[:, 128:192])
    {
        float v = (t < 64) ? ZS2[m * 192 + 128 + t] : -1e30f;
        float mx = v;
        for (int o = 16; o > 0; o >>= 1) mx = fmaxf(mx, __shfl_xor_sync(0xffffffffu, mx, o));
        if (t < 64 && (t & 31) == 0) sh[128 + (t >> 5)] = mx;
        __syncthreads();
        float MX = fmaxf(sh[128], sh[129]);
        float e = (t < 64) ? expf(v - MX) : 0.f;
        float ssum = e;
        for (int o = 16; o > 0; o >>= 1) ssum += __shfl_xor_sync(0xffffffffu, ssum, o);
        if (t < 64 && (t & 31) == 0) sh[128 + (t >> 5)] = ssum;
        __syncthreads();
        if (t < 64) S2[m * 64 + t] = e / (sh[128] + sh[129]);
        __syncthreads();
    }
    gbar(base + 5);
    // P5: V2 = A2 @ S2 ; xp2 = S2^T @ z2   (z2 = ZS2[:, :128])
    {
        if (t < 64) {
            const float* a = A2 + m * 256;
            float acc = 0.f;
#pragma unroll 8
            for (int k = 0; k < 256; k++) acc += a[k] * S2[k * 64 + t];
            V2[m * 64 + t] = acc;
        }
        if (m < 64) {
            float acc = 0.f;
#pragma unroll 8
            for (int k = 0; k < 256; k++) acc += S2[k * 64 + m] * ZS2[k * 192 + t];
            xp2[m * 128 + t] = acc;
        }
    }
    gbar(base + 6);
    // P6: A3 = S2^T @ V2
    if (m < 64 && t < 64) {
        float acc = 0.f;
#pragma unroll 8
        for (int k = 0; k < 256; k++) acc += S2[k * 64 + m] * V2[k * 64 + t];
        A3[m * 64 + t] = acc;
    }
    gbar(base + 7);
    // P7: T = xp2 @ Wg3 (64x128, K=128) ; ca3 = colsum(A3)
    if (m < 64) {
        const float* a = xp2 + m * 128;
        float acc = 0.f;
#pragma unroll 8
        for (int k = 0; k < 128; k++) acc += a[k] * Wg3[k * 128 + t];
        T[m * 128 + t] = acc;
    } else if (m == 64 && t < 64) {
        float s = 0.f;
        for (int r = 0; r < 64; r++) s += A3[r * 64 + t];
        ca3[t] = s;
    }
    gbar(base + 8);
    // P8: X3 = A3 @ T + bg3   (K=64)
    if (m < 64) {
        const float* a = A3 + m * 64;
        float acc = 0.f;
#pragma unroll 8
        for (int k = 0; k < 64; k++) acc += a[k] * T[k * 128 + t];
        X3[m * 128 + t] = acc + bg3[t];
    }
    gbar(base + 9);
    // P9: Z3(=T4) = X3 @ Wd31   (K=128)
    if (m < 64) {
        const float* a = X3 + m * 128;
        float acc = 0.f;
#pragma unroll 8
        for (int k = 0; k < 128; k++) acc += a[k] * Wd31[k * 128 + t];
        Z3[m * 128 + t] = acc;
    }
    gbar(base + 10);
    // P10: colsum(A3@T4 + bd31) = ca3@T4 + 64*bd31 -> fc -> log_softmax
    if (m == 0) {
        float s = 64.f * bd31[t];
        for (int k = 0; k < 64; k++) s += ca3[k] * Z3[k * 128 + t];
        sh[t] = s;
        __syncthreads();
        if (t < 10) {
            float a = bfc[t];
            for (int k = 0; k < 128; k++) a += sh[k] * Wfc[k * 10 + t];
            logits[t] = a;
        }
        __syncthreads();
        if (t == 0) {
            float mx = logits[0];
            for (int i = 1; i < 10; i++) mx = fmaxf(mx, logits[i]);
            float se = 0.f;
            for (int i = 0; i < 10; i++) se += expf(logits[i] - mx);
            red = mx + logf(se);
        }
        __syncthreads();
        if (t < 10) out[t] = logits[t] - red;
    }
}

// ---------------------------------------------------------------------------
static void* sym(const void* s) {
    void* p = nullptr;
    cudaGetSymbolAddress(&p, s);
    return p;
}

extern "C" void kernel_launch(void* const* d_in, const int* in_sizes, int n_in,
                              void* d_out, int out_size) {
    const float* x      = (const float*)d_in[0];
    const float* adj    = (const float*)d_in[1];
    const float* W_gcn1 = (const float*)d_in[2];
    const float* b_gcn1 = (const float*)d_in[3];
    const float* W_d11  = (const float*)d_in[4];
    const float* b_d11  = (const float*)d_in[5];
    const float* W_d12  = (const float*)d_in[6];
    const float* b_d12  = (const float*)d_in[7];
    const float* W_gcn2 = (const float*)d_in[8];
    const float* b_gcn2 = (const float*)d_in[9];
    const float* W_d21  = (const float*)d_in[10];
    const float* b_d21  = (const float*)d_in[11];
    const float* W_d22  = (const float*)d_in[12];
    const float* b_d22  = (const float*)d_in[13];
    const float* W_gcn3 = (const float*)d_in[14];
    const float* b_gcn3 = (const float*)d_in[15];
    const float* W_d31  = (const float*)d_in[16];
    const float* b_d31  = (const float*)d_in[17];
    // d_in[18]=W_d32, d_in[19]=b_d32: softmax over width-1 axis == 1 exactly -> unused
    const float* W_fc   = (const float*)d_in[20];
    const float* b_fc   = (const float*)d_in[21];
    float* out = (float*)d_out;

    float* dD    = (float*)sym(g_d);
    int*   dCnt  = (int*)sym(g_cnt);
    int*   dCi   = (int*)sym(g_colidx);
    float* H0s   = (float*)sym(g_H0s);
    float* X1s   = (float*)sym(g_X1s);
    float* ZS    = (float*)sym(g_ZS);
    float* S1    = (float*)sym(g_S1);
    float* S1s   = (float*)sym(g_S1s);
    float* U     = (float*)sym(g_U);
    float* Wcat  = (float*)sym(g_Wcat);
    float* bcat  = (float*)sym(g_bcat);
    float* xp1   = (float*)sym(g_xp1);
    float* A2    = (float*)sym(g_A2);
    float* T     = (float*)sym(g_T);
    float* X2    = (float*)sym(g_X2);
    float* ZS2   = (float*)sym(g_ZS2);
    float* S2    = (float*)sym(g_S2);
    float* V2    = (float*)sym(g_V2);
    float* xp2   = (float*)sym(g_xp2);
    float* A3    = (float*)sym(g_A3);
    float* X3    = (float*)sym(g_X3);
    float* Z3    = (float*)sym(g_Z3);
    float* ca3   = (float*)sym(g_ca3);
    __nv_bfloat16* xhi  = (__nv_bfloat16*)sym(g_xhi);
    __nv_bfloat16* xlo  = (__nv_bfloat16*)sym(g_xlo);
    __nv_bfloat16* w1hi = (__nv_bfloat16*)sym(g_w1hi);
    __nv_bfloat16* w1lo = (__nv_bfloat16*)sym(g_w1lo);
    __nv_bfloat16* Yhi  = (__nv_bfloat16*)sym(g_Yhi);
    __nv_bfloat16* Ylo  = (__nv_bfloat16*)sym(g_Ylo);
    __nv_bfloat16* wchi = (__nv_bfloat16*)sym(g_wchi);
    __nv_bfloat16* wclo = (__nv_bfloat16*)sym(g_wclo);

    // ---- ELL build + degree factors (one adjacency pass) ----
    ell_build<<<NN, 256>>>(adj, dCi, dCnt, dD);

    // ---- bf16 hi/lo splits (K padded 784 -> 800) ----
    cvt_pad_cols<<<(NN * KP1 + 255) / 256, 256>>>(x, xhi, xlo, NN, 784, KP1);
    cvt_pad_rows<<<(KP1 * 256 + 255) / 256, 256>>>(W_gcn1, w1hi, w1lo, 784, KP1, 256);

    // ---- level 1 ----
    wgemm3<<<dim3(256 / 64, NN / 64), 128>>>(xhi, xlo, w1hi, w1lo, H0s,
                                             NN, 256, KP1, nullptr, dD);
    spmm4<<<NN, 256>>>(dCi, dCnt, dD, (const float4*)H0s, (float4*)X1s,
                       (const float4*)b_gcn1, nullptr, nullptr, 1);
    spmm4<<<NN, 256>>>(dCi, dCnt, dD, (const float4*)X1s, nullptr, nullptr,
                       (__nv_bfloat162*)Yhi, (__nv_bfloat162*)Ylo, 2);

    pack_wcat<<<(256 * 384 + 255) / 256, 256>>>(W_d11, W_d12, b_d11, b_d12, Wcat, bcat);
    cvt_split4<<<(256 * 384 / 4 + 255) / 256, 256>>>((const float4*)Wcat,
        (__nv_bfloat162*)wchi, (__nv_bfloat162*)wclo, 256 * 384 / 4);
    wgemm3<<<dim3(384 / 64, NN / 64), 128>>>(Yhi, Ylo, wchi, wclo, ZS,
                                             NN, 384, 256, bcat, nullptr);

    softmax_dual<<<NN, 256>>>(ZS, 384, 128, dD, S1, S1s);
    spmm4<<<NN, 256>>>(dCi, dCnt, dD, (const float4*)S1s, (float4*)U,
                       nullptr, nullptr, nullptr, 0);

    zero2_kernel<<<(256 * 128 + 256 * 256 + 255) / 256, 256>>>(xp1, 256 * 128, A2, 256 * 256);
    tgemm_kernel<<<dim3(8, 32), 128>>>(S1, 256, ZS, 384, xp1, 128, NN);  // s1^T @ z1
    tgemm_kernel<<<dim3(8, 32), 256>>>(S1, 256, U, 256, A2, 256, NN);    // s1^T @ U

    // ---- fused level-2/3 tail (replaces 14 launches) ----
    tail_fused<<<256, 128>>>(xp1, A2,
                             W_gcn2, b_gcn2, W_d21, b_d21, W_d22, b_d22,
                             W_gcn3, b_gcn3, W_d31, b_d31, W_fc, b_fc,
                             T, X2, ZS2, S2, V2, xp2, A3, X3, Z3, ca3, out);
}

// round 10
// speedup vs baseline: 1.2197x; 1.2197x over previous
#include <cuda_runtime.h>
#include <cuda_bf16.h>
#include <mma.h>
#include <math.h>

using namespace nvcuda;

#define NN 8192
#define ELLW 320
#define KP1 800   // K=784 padded to multiple of 32

// padded smem strides (bank-conflict-free LDSM)
#define LDA_S 40   // A tile row stride in bf16 (80B)
#define LDB_S 72   // B tile row stride in bf16 (144B)

// ---------------- scratch (device globals; no allocation allowed) ----------
__device__ float g_d[NN];
__device__ int   g_cnt[NN];
__device__ int   g_colidx[NN * ELLW];
__device__ float g_H0s[NN * 256];
__device__ float g_X1s[NN * 256];
__device__ float g_ZS[NN * 384];
__device__ float g_S1 [NN * 256];
__device__ float g_S1s[NN * 256];
__device__ float g_U [NN * 256];
__device__ float g_bcat [384];
__device__ float g_Wcat2[128 * 192];
__device__ float g_bcat2[192];
__device__ float g_xp1[256 * 128];
__device__ float g_A2 [256 * 256];
__device__ float g_T  [256 * 256];
__device__ float g_X2 [256 * 128];
__device__ float g_ZS2[256 * 192];
__device__ float g_S2 [256 * 64];
__device__ float g_V2 [256 * 64];
__device__ float g_xp2[64 * 128];
__device__ float g_A3 [64 * 64];
__device__ float g_X3 [64 * 128];
__device__ float g_Z3 [64 * 128];

// bf16 hi/lo split buffers
__device__ __align__(16) __nv_bfloat16 g_xhi[NN * KP1];
__device__ __align__(16) __nv_bfloat16 g_xlo[NN * KP1];
__device__ __align__(16) __nv_bfloat16 g_w1hi[KP1 * 256];
__device__ __align__(16) __nv_bfloat16 g_w1lo[KP1 * 256];
__device__ __align__(16) __nv_bfloat16 g_Yhi[NN * 256];
__device__ __align__(16) __nv_bfloat16 g_Ylo[NN * 256];
__device__ __align__(16) __nv_bfloat16 g_wchi[256 * 384];
__device__ __align__(16) __nv_bfloat16 g_wclo[256 * 384];

// ---------------- one-pass ELL build + degrees ------------------------------
__global__ void ell_build(const float* __restrict__ adj, int* __restrict__ colidx,
                          int* __restrict__ cnt, float* __restrict__ drs) {
    int row = blockIdx.x;
    int tid = threadIdx.x, lane = tid & 31, w = tid >> 5;
    const float* ar = adj + (size_t)row * NN;
    __shared__ int woff[9];
    int base = w * 1024;
    unsigned msk = 0;
#pragma unroll
    for (int s = 0; s < 32; s++) {
        float v = ar[base + s * 32 + lane];
        msk |= (v != 0.f) ? (1u << s) : 0u;
    }
    int c = __popc(msk);
    for (int o = 16; o > 0; o >>= 1) c += __shfl_down_sync(0xffffffffu, c, o);
    if (lane == 0) woff[w + 1] = c;
    __syncthreads();
    if (tid == 0) {
        woff[0] = 0;
        for (int i = 1; i <= 8; i++) woff[i] += woff[i - 1];
    }
    __syncthreads();
    int off = woff[w];
    unsigned ltmask = (1u << lane) - 1u;
    int* ci = colidx + (size_t)row * ELLW;
#pragma unroll
    for (int s = 0; s < 32; s++) {
        unsigned bit = (msk >> s) & 1u;
        unsigned m = __ballot_sync(0xffffffffu, bit);
        if (bit) {
            int pos = off + __popc(m & ltmask);
            if (pos < ELLW) ci[pos] = base + s * 32 + lane;
        }
        off += __popc(m);
    }
    if (tid == 0) {
        int tot = woff[8];
        cnt[row] = tot;
        drs[row] = rsqrtf((float)tot);
    }
}

// ---------------- bf16 split conversions ------------------------------------
__global__ void cvt_pad_cols(const float* __restrict__ in,
                             __nv_bfloat16* __restrict__ hi,
                             __nv_bfloat16* __restrict__ lo,
                             int M, int K, int KPp) {
    int idx = blockIdx.x * blockDim.x + threadIdx.x;
    if (idx >= M * KPp) return;
    int r = idx / KPp, c = idx - r * KPp;
    float v = (c < K) ? in[(size_t)r * K + c] : 0.f;
    __nv_bfloat16 h = __float2bfloat16(v);
    hi[idx] = h;
    lo[idx] = __float2bfloat16(v - __bfloat162float(h));
}

__global__ void cvt_pad_rows(const float* __restrict__ in,
                             __nv_bfloat16* __restrict__ hi,
                             __nv_bfloat16* __restrict__ lo,
                             int K, int KPp, int N) {
    int idx = blockIdx.x * blockDim.x + threadIdx.x;
    if (idx >= KPp * N) return;
    int r = idx / N;
    float v = (r < K) ? in[idx] : 0.f;
    __nv_bfloat16 h = __float2bfloat16(v);
    hi[idx] = h;
    lo[idx] = __float2bfloat16(v - __bfloat162float(h));
}

// pack [W_d11 | W_d12] and split to bf16 hi/lo in one pass; also bcat
__global__ void pack_wcat_split(const float* __restrict__ Wd11,
                                const float* __restrict__ Wd12,
                                const float* __restrict__ bd11,
                                const float* __restrict__ bd12,
                                __nv_bfloat16* __restrict__ hi,
                                __nv_bfloat16* __restrict__ lo,
                                float* __restrict__ bcat) {
    int idx = blockIdx.x * blockDim.x + threadIdx.x;
    if (idx < 256 * 384) {
        int k = idx / 384, n = idx % 384;
        float v = (n < 128) ? Wd11[k * 128 + n] : Wd12[k * 256 + (n - 128)];
        __nv_bfloat16 h = __float2bfloat16(v);
        hi[idx] = h;
        lo[idx] = __float2bfloat16(v - __bfloat162float(h));
    }
    if (idx < 384) bcat[idx] = (idx < 128) ? bd11[idx] : bd12[idx - 128];
}

// ---------------- tensor GEMM: 64x64 tile, padded smem, 2-stage cp.async ---
__device__ __forceinline__ void cp16(void* sp, const void* gp) {
    unsigned a = (unsigned)__cvta_generic_to_shared(sp);
    asm volatile("cp.async.cg.shared.global [%0], [%1], 16;\n" :: "r"(a), "l"(gp));
}

#define STG_STRIDE 19456

__global__ __launch_bounds__(128) void wgemm3(const __nv_bfloat16* __restrict__ Ahi,
                                              const __nv_bfloat16* __restrict__ Alo,
                                              const __nv_bfloat16* __restrict__ Bhi,
                                              const __nv_bfloat16* __restrict__ Blo,
                                              float* __restrict__ C,
                                              int M, int N, int KPk,
                                              const float* __restrict__ bias,
                                              const float* __restrict__ rowscale) {
    __shared__ __align__(16) char smem[2 * STG_STRIDE];
    int tid = threadIdx.x;
    int wid = tid >> 5, lane = tid & 31;
    int wm = wid & 1, wn = wid >> 1;
    int bm = blockIdx.y * 64, bn = blockIdx.x * 64;

    wmma::fragment<wmma::accumulator, 16, 16, 16, float> acc[2][2];
#pragma unroll
    for (int i = 0; i < 2; i++)
#pragma unroll
        for (int j = 0; j < 2; j++) wmma::fill_fragment(acc[i][j], 0.f);

    int a_r = tid >> 2, a_c = (tid & 3) * 8;
    int b_r = tid >> 3, b_c = (tid & 7) * 8;

    int nk = KPk >> 5;
    auto sAhi = [&](int s) { return (__nv_bfloat16*)(smem + s * STG_STRIDE); };
    auto sAlo = [&](int s) { return (__nv_bfloat16*)(smem + s * STG_STRIDE + 5120); };
    auto sBhi = [&](int s) { return (__nv_bfloat16*)(smem + s * STG_STRIDE + 10240); };
    auto sBlo = [&](int s) { return (__nv_bfloat16*)(smem + s * STG_STRIDE + 14848); };

    auto load_stage = [&](int s, int k0) {
        __nv_bfloat16* ah = sAhi(s); __nv_bfloat16* al = sAlo(s);
        __nv_bfloat16* bh = sBhi(s); __nv_bfloat16* bl = sBlo(s);
#pragma unroll
        for (int i = 0; i < 2; i++) {
            int r = a_r + i * 32;
            cp16(&ah[r * LDA_S + a_c], &Ahi[(size_t)(bm + r) * KPk + k0 + a_c]);
            cp16(&al[r * LDA_S + a_c], &Alo[(size_t)(bm + r) * KPk + k0 + a_c]);
        }
#pragma unroll
        for (int i = 0; i < 2; i++) {
            int r = b_r + i * 16;
            cp16(&bh[r * LDB_S + b_c], &Bhi[(size_t)(k0 + r) * N + bn + b_c]);
            cp16(&bl[r * LDB_S + b_c], &Blo[(size_t)(k0 + r) * N + bn + b_c]);
        }
        asm volatile("cp.async.commit_group;\n");
    };

    load_stage(0, 0);
    for (int it = 0; it < nk; it++) {
        if (it + 1 < nk) {
            load_stage((it + 1) & 1, (it + 1) * 32);
            asm volatile("cp.async.wait_group 1;\n");
        } else {
            asm volatile("cp.async.wait_group 0;\n");
        }
        __syncthreads();
        int s = it & 1;
        __nv_bfloat16* ah_ = sAhi(s); __nv_bfloat16* al_ = sAlo(s);
        __nv_bfloat16* bh_ = sBhi(s); __nv_bfloat16* bl_ = sBlo(s);
#pragma unroll
        for (int ks = 0; ks < 2; ks++) {
            wmma::fragment<wmma::matrix_b, 16, 16, 16, __nv_bfloat16, wmma::row_major> bh[2], bl[2];
#pragma unroll
            for (int j = 0; j < 2; j++) {
                wmma::load_matrix_sync(bh[j], bh_ + (ks * 16) * LDB_S + wn * 32 + j * 16, LDB_S);
                wmma::load_matrix_sync(bl[j], bl_ + (ks * 16) * LDB_S + wn * 32 + j * 16, LDB_S);
            }
#pragma unroll
            for (int i = 0; i < 2; i++) {
                wmma::fragment<wmma::matrix_a, 16, 16, 16, __nv_bfloat16, wmma::row_major> ah, al;
                wmma::load_matrix_sync(ah, ah_ + (wm * 32 + i * 16) * LDA_S + ks * 16, LDA_S);
                wmma::load_matrix_sync(al, al_ + (wm * 32 + i * 16) * LDA_S + ks * 16, LDA_S);
#pragma unroll
                for (int j = 0; j < 2; j++) {
                    wmma::mma_sync(acc[i][j], ah, bh[j], acc[i][j]);
                    wmma::mma_sync(acc[i][j], ah, bl[j], acc[i][j]);
                    wmma::mma_sync(acc[i][j], al, bh[j], acc[i][j]);
                }
            }
        }
        __syncthreads();
    }

    float* myout = (float*)smem + wid * (32 * 36);
#pragma unroll
    for (int i = 0; i < 2; i++)
#pragma unroll
        for (int j = 0; j < 2; j++)
            wmma::store_matrix_sync(myout + i * 16 * 36 + j * 16, acc[i][j], 36,
                                    wmma::mem_row_major);
    int colg = bn + wn * 32 + lane;
    float bb = bias ? bias[colg] : 0.f;
#pragma unroll 4
    for (int rr = 0; rr < 32; rr++) {
        int rowg = bm + wm * 32 + rr;
        float sc = rowscale ? rowscale[rowg] : 1.f;
        C[(size_t)rowg * N + colg] = sc * (myout[rr * 36 + lane] + bb);
    }
}

// ---------------- SpMM ------------------------------------------------------
__global__ __launch_bounds__(256) void spmm4(const int* __restrict__ colidx,
                                             const int* __restrict__ cnt,
                                             const float* __restrict__ drs,
                                             const float4* __restrict__ B,
                                             float4* __restrict__ out,
                                             const float4* __restrict__ bias,
                                             __nv_bfloat162* __restrict__ outhi,
                                             __nv_bfloat162* __restrict__ outlo,
                                             int mode) {
    __shared__ int sidx[ELLW];
    __shared__ float4 sred[192];
    int row = blockIdx.x;
    int tid = threadIdx.x;
    int g = tid >> 6, c = tid & 63;
    int e = cnt[row];
    if (e > ELLW) e = ELLW;
    for (int i = tid; i < e; i += 256) sidx[i] = colidx[(size_t)row * ELLW + i];
    __syncthreads();

    float4 acc = make_float4(0.f, 0.f, 0.f, 0.f);
    int p = g;
    for (; p + 8 <= e; p += 8) {
        int j0 = sidx[p], j1 = sidx[p + 4];
        float4 v0 = B[(size_t)j0 * 64 + c];
        float4 v1 = B[(size_t)j1 * 64 + c];
        acc.x += v0.x; acc.y += v0.y; acc.z += v0.z; acc.w += v0.w;
        acc.x += v1.x; acc.y += v1.y; acc.z += v1.z; acc.w += v1.w;
    }
    for (; p < e; p += 4) {
        int j = sidx[p];
        float4 v = B[(size_t)j * 64 + c];
        acc.x += v.x; acc.y += v.y; acc.z += v.z; acc.w += v.w;
    }
    if (g > 0) sred[(g - 1) * 64 + c] = acc;
    __syncthreads();
    if (g == 0) {
        float4 a1 = sred[c], a2 = sred[64 + c], a3 = sred[128 + c];
        acc.x += a1.x + a2.x + a3.x;
        acc.y += a1.y + a2.y + a3.y;
        acc.z += a1.z + a2.z + a3.z;
        acc.w += a1.w + a2.w + a3.w;
        float s = drs[row];
        float4 r;
        if (mode == 1) {
            float4 b = bias[c];
            r.x = s * (s * acc.x + b.x);
            r.y = s * (s * acc.y + b.y);
            r.z = s * (s * acc.z + b.z);
            r.w = s * (s * acc.w + b.w);
        } else {
            r.x = s * acc.x; r.y = s * acc.y; r.z = s * acc.z; r.w = s * acc.w;
        }
        if (mode == 2) {
            __nv_bfloat16 h0 = __float2bfloat16(r.x);
            __nv_bfloat16 h1 = __float2bfloat16(r.y);
            __nv_bfloat16 h2 = __float2bfloat16(r.z);
            __nv_bfloat16 h3 = __float2bfloat16(r.w);
            outhi[(size_t)row * 128 + 2 * c]     = __nv_bfloat162(h0, h1);
            outhi[(size_t)row * 128 + 2 * c + 1] = __nv_bfloat162(h2, h3);
            outlo[(size_t)row * 128 + 2 * c] = __nv_bfloat162(
                __float2bfloat16(r.x - __bfloat162float(h0)),
                __float2bfloat16(r.y - __bfloat162float(h1)));
            outlo[(size_t)row * 128 + 2 * c + 1] = __nv_bfloat162(
                __float2bfloat16(r.z - __bfloat162float(h2)),
                __float2bfloat16(r.w - __bfloat162float(h3)));
        } else {
            out[(size_t)row * 64 + c] = r;
        }
    }
}

// ---------------- softmaxes --------------------------------------------------
__global__ void softmax_dual(const float* __restrict__ in, int ldi, int off,
                             const float* __restrict__ drs,
                             float* __restrict__ out, float* __restrict__ outs) {
    int row = blockIdx.x, t = threadIdx.x;
    __shared__ float sm[8];
    float v = in[(size_t)row * ldi + off + t];
    float m = v;
    for (int o = 16; o > 0; o >>= 1) m = fmaxf(m, __shfl_xor_sync(0xffffffffu, m, o));
    if ((t & 31) == 0) sm[t >> 5] = m;
    __syncthreads();
    if (t < 8) {
        float mm = sm[t];
        for (int o = 4; o > 0; o >>= 1) mm = fmaxf(mm, __shfl_xor_sync(0xffu, mm, o));
        sm[t] = mm;
    }
    __syncthreads();
    float mx = sm[0];
    __syncthreads();
    float e = expf(v - mx);
    float s = e;
    for (int o = 16; o > 0; o >>= 1) s += __shfl_xor_sync(0xffffffffu, s, o);
    if ((t & 31) == 0) sm[t >> 5] = s;
    __syncthreads();
    if (t < 8) {
        float ss = sm[t];
        for (int o = 4; o > 0; o >>= 1) ss += __shfl_xor_sync(0xffu, ss, o);
        sm[t] = ss;
    }
    __syncthreads();
    float r = e / sm[0];
    out[(size_t)row * 256 + t] = r;
    outs[(size_t)row * 256 + t] = drs[row] * r;
}

__global__ void softmax_small(const float* __restrict__ in, int ldi, int off,
                              float* __restrict__ out, int ldo) {
    int row = blockIdx.x, t = threadIdx.x;
    __shared__ float sm[2];
    float v = in[(size_t)row * ldi + off + t];
    float m = v;
    for (int o = 16; o > 0; o >>= 1) m = fmaxf(m, __shfl_xor_sync(0xffffffffu, m, o));
    if ((t & 31) == 0) sm[t >> 5] = m;
    __syncthreads();
    float mx = fmaxf(sm[0], sm[1]);
    float e = expf(v - mx);
    float s = e;
    for (int o = 16; o > 0; o >>= 1) s += __shfl_xor_sync(0xffffffffu, s, o);
    if ((t & 31) == 0) sm[t >> 5] = s;
    __syncthreads();
    out[(size_t)row * ldo + t] = e / (sm[0] + sm[1]);
}

// ---------------- transpose GEMM: C += S^T @ V (32 rows/block) --------------
__global__ void tgemm_kernel(const float* __restrict__ S, int lds,
                             const float* __restrict__ V, int ldv,
                             float* __restrict__ C, int ldc, int K) {
    int ag = blockIdx.x * 32;
    int kchunk = K / gridDim.y;
    int k0 = blockIdx.y * kchunk, k1 = k0 + kchunk;
    int t = threadIdx.x;
    float acc[32];
#pragma unroll
    for (int u = 0; u < 32; u++) acc[u] = 0.f;
    for (int k = k0; k < k1; k++) {
        float v = V[(size_t)k * ldv + t];
        const float4* sp = (const float4*)(S + (size_t)k * lds + ag);
#pragma unroll
        for (int q = 0; q < 8; q++) {
            float4 s4 = sp[q];
            acc[q * 4 + 0] += s4.x * v;
            acc[q * 4 + 1] += s4.y * v;
            acc[q * 4 + 2] += s4.z * v;
            acc[q * 4 + 3] += s4.w * v;
        }
    }
#pragma unroll
    for (int u = 0; u < 32; u++) atomicAdd(&C[(ag + u) * ldc + t], acc[u]);
}

__global__ void zero2_kernel(float* a, int na, float* b, int nb) {
    int i = blockIdx.x * blockDim.x + threadIdx.x;
    if (i < na) a[i] = 0.f;
    else if (i < na + nb) b[i - na] = 0.f;
}

// ---------------- small dense GEMMs -----------------------------------------
__global__ void gemm_small(const float* __restrict__ A, int lda,
                           const float* __restrict__ B, int ldb,
                           float* __restrict__ C, int ldc, int K,
                           const float* __restrict__ bias) {
    int m = blockIdx.x, t = threadIdx.x;
    const float* a = A + (size_t)m * lda;
    float acc = 0.f;
#pragma unroll 8
    for (int k = 0; k < K; k++) acc += a[k] * B[(size_t)k * ldb + t];
    if (bias) acc += bias[t];
    C[(size_t)m * ldc + t] = acc;
}

__global__ void gemm_small_AT(const float* __restrict__ A, int lda,
                              const float* __restrict__ B, int ldb,
                              float* __restrict__ C, int ldc, int K) {
    int m = blockIdx.x, t = threadIdx.x;
    float acc = 0.f;
#pragma unroll 8
    for (int k = 0; k < K; k++) acc += A[(size_t)k * lda + m] * B[(size_t)k * ldb + t];
    C[(size_t)m * ldc + t] = acc;
}

// ---------------- pack [W_d21 | W_d22] ---------------------------------------
__global__ void pack_wcat2(const float* __restrict__ Wd21, const float* __restrict__ Wd22,
                           const float* __restrict__ bd21, const float* __restrict__ bd22,
                           float* __restrict__ Wcat, float* __restrict__ bcat) {
    int idx = blockIdx.x * blockDim.x + threadIdx.x;
    if (idx < 128 * 192) {
        int k = idx / 192, n = idx % 192;
        Wcat[idx] = (n < 128) ? Wd21[k * 128 + n] : Wd22[k * 64 + (n - 128)];
    }
    if (idx < 192) bcat[idx] = (idx < 128) ? bd21[idx] : bd22[idx - 128];
}

// ---------------- final ------------------------------------------------------
__global__ void final_kernel(const float* __restrict__ Z3, const float* __restrict__ Wfc,
                             const float* __restrict__ bfc, float* __restrict__ out) {
    __shared__ float xf[128];
    __shared__ float logits[10];
    __shared__ float red;
    int t = threadIdx.x;
    float s = 0.f;
    for (int r = 0; r < 64; r++) s += Z3[r * 128 + t];
    xf[t] = s;
    __syncthreads();
    if (t < 10) {
        float a = bfc[t];
        for (int k = 0; k < 128; k++) a += xf[k] * Wfc[k * 10 + t];
        logits[t] = a;
    }
    __syncthreads();
    if (t == 0) {
        float mx = logits[0];
        for (int i = 1; i < 10; i++) mx = fmaxf(mx, logits[i]);
        float se = 0.f;
        for (int i = 0; i < 10; i++) se += expf(logits[i] - mx);
        red = mx + logf(se);
    }
    __syncthreads();
    if (t < 10) out[t] = logits[t] - red;
}

// ---------------------------------------------------------------------------
static void* sym(const void* s) {
    void* p = nullptr;
    cudaGetSymbolAddress(&p, s);
    return p;
}

extern "C" void kernel_launch(void* const* d_in, const int* in_sizes, int n_in,
                              void* d_out, int out_size) {
    const float* x      = (const float*)d_in[0];
    const float* adj    = (const float*)d_in[1];
    const float* W_gcn1 = (const float*)d_in[2];
    const float* b_gcn1 = (const float*)d_in[3];
    const float* W_d11  = (const float*)d_in[4];
    const float* b_d11  = (const float*)d_in[5];
    const float* W_d12  = (const float*)d_in[6];
    const float* b_d12  = (const float*)d_in[7];
    const float* W_gcn2 = (const float*)d_in[8];
    const float* b_gcn2 = (const float*)d_in[9];
    const float* W_d21  = (const float*)d_in[10];
    const float* b_d21  = (const float*)d_in[11];
    const float* W_d22  = (const float*)d_in[12];
    const float* b_d22  = (const float*)d_in[13];
    const float* W_gcn3 = (const float*)d_in[14];
    const float* b_gcn3 = (const float*)d_in[15];
    const float* W_d31  = (const float*)d_in[16];
    const float* b_d31  = (const float*)d_in[17];
    // d_in[18]=W_d32, d_in[19]=b_d32: softmax over width-1 axis == 1 exactly -> unused
    const float* W_fc   = (const float*)d_in[20];
    const float* b_fc   = (const float*)d_in[21];
    float* out = (float*)d_out;

    float* dD    = (float*)sym(g_d);
    int*   dCnt  = (int*)sym(g_cnt);
    int*   dCi   = (int*)sym(g_colidx);
    float* H0s   = (float*)sym(g_H0s);
    float* X1s   = (float*)sym(g_X1s);
    float* ZS    = (float*)sym(g_ZS);
    float* S1    = (float*)sym(g_S1);
    float* S1s   = (float*)sym(g_S1s);
    float* U     = (float*)sym(g_U);
    float* bcat  = (float*)sym(g_bcat);
    float* Wcat2 = (float*)sym(g_Wcat2);
    float* bcat2 = (float*)sym(g_bcat2);
    float* xp1   = (float*)sym(g_xp1);
    float* A2    = (float*)sym(g_A2);
    float* T     = (float*)sym(g_T);
    float* X2    = (float*)sym(g_X2);
    float* ZS2   = (float*)sym(g_ZS2);
    float* S2    = (float*)sym(g_S2);
    float* V2    = (float*)sym(g_V2);
    float* xp2   = (float*)sym(g_xp2);
    float* A3    = (float*)sym(g_A3);
    float* X3    = (float*)sym(g_X3);
    float* Z3    = (float*)sym(g_Z3);
    __nv_bfloat16* xhi  = (__nv_bfloat16*)sym(g_xhi);
    __nv_bfloat16* xlo  = (__nv_bfloat16*)sym(g_xlo);
    __nv_bfloat16* w1hi = (__nv_bfloat16*)sym(g_w1hi);
    __nv_bfloat16* w1lo = (__nv_bfloat16*)sym(g_w1lo);
    __nv_bfloat16* Yhi  = (__nv_bfloat16*)sym(g_Yhi);
    __nv_bfloat16* Ylo  = (__nv_bfloat16*)sym(g_Ylo);
    __nv_bfloat16* wchi = (__nv_bfloat16*)sym(g_wchi);
    __nv_bfloat16* wclo = (__nv_bfloat16*)sym(g_wclo);

    // ---- ELL build + degree factors (one adjacency pass) ----
    ell_build<<<NN, 256>>>(adj, dCi, dCnt, dD);

    // ---- bf16 hi/lo splits (K padded 784 -> 800) ----
    cvt_pad_cols<<<(NN * KP1 + 255) / 256, 256>>>(x, xhi, xlo, NN, 784, KP1);
    cvt_pad_rows<<<(KP1 * 256 + 255) / 256, 256>>>(W_gcn1, w1hi, w1lo, 784, KP1, 256);

    // ---- level 1 ----
    wgemm3<<<dim3(256 / 64, NN / 64), 128>>>(xhi, xlo, w1hi, w1lo, H0s,
                                             NN, 256, KP1, nullptr, dD);
    spmm4<<<NN, 256>>>(dCi, dCnt, dD, (const float4*)H0s, (float4*)X1s,
                       (const float4*)b_gcn1, nullptr, nullptr, 1);
    spmm4<<<NN, 256>>>(dCi, dCnt, dD, (const float4*)X1s, nullptr, nullptr,
                       (__nv_bfloat162*)Yhi, (__nv_bfloat162*)Ylo, 2);

    pack_wcat_split<<<(256 * 384 + 255) / 256, 256>>>(W_d11, W_d12, b_d11, b_d12,
                                                      wchi, wclo, bcat);
    wgemm3<<<dim3(384 / 64, NN / 64), 128>>>(Yhi, Ylo, wchi, wclo, ZS,
                                             NN, 384, 256, bcat, nullptr);

    softmax_dual<<<NN, 256>>>(ZS, 384, 128, dD, S1, S1s);
    spmm4<<<NN, 256>>>(dCi, dCnt, dD, (const float4*)S1s, (float4*)U,
                       nullptr, nullptr, nullptr, 0);

    zero2_kernel<<<(256 * 128 + 256 * 256 + 255) / 256, 256>>>(xp1, 256 * 128, A2, 256 * 256);
    tgemm_kernel<<<dim3(8, 32), 128>>>(S1, 256, ZS, 384, xp1, 128, NN);  // s1^T @ z1
    tgemm_kernel<<<dim3(8, 32), 256>>>(S1, 256, U, 256, A2, 256, NN);    // s1^T @ U

    // ---- level 2 (256 nodes) ----
    pack_wcat2<<<(128 * 192 + 255) / 256, 256>>>(W_d21, W_d22, b_d21, b_d22, Wcat2, bcat2);
    gemm_small<<<256, 128>>>(xp1, 128, W_gcn2, 128, T, 128, 128, nullptr);
    gemm_small<<<256, 128>>>(A2, 256, T, 128, X2, 128, 256, b_gcn2);
    gemm_small<<<256, 192>>>(X2, 128, Wcat2, 192, T, 192, 128, nullptr);
    gemm_small<<<256, 192>>>(A2, 256, T, 192, ZS2, 192, 256, bcat2);
    softmax_small<<<256, 64>>>(ZS2, 192, 128, S2, 64);
    gemm_small_AT<<<64, 128>>>(S2, 64, ZS2, 192, xp2, 128, 256);
    gemm_small<<<256, 64>>>(A2, 256, S2, 64, V2, 64, 256, nullptr);
    gemm_small_AT<<<64, 64>>>(S2, 64, V2, 64, A3, 64, 256);

    // ---- level 3 (64 nodes) ----
    gemm_small<<<64, 128>>>(xp2, 128, W_gcn3, 128, T, 128, 128, nullptr);
    gemm_small<<<64, 128>>>(A3, 64, T, 128, X3, 128, 64, b_gcn3);
    gemm_small<<<64, 128>>>(X3, 128, W_d31, 128, T, 128, 128, nullptr);
    gemm_small<<<64, 128>>>(A3, 64, T, 128, Z3, 128, 64, b_d31);

    // s3 == ones -> final = colsum(Z3) @ W_fc + b_fc -> log_softmax
    final_kernel<<<1, 128>>>(Z3, W_fc, b_fc, out);
}

// round 11
// speedup vs baseline: 1.3851x; 1.1357x over previous
#include <cuda_runtime.h>
#include <cuda_bf16.h>
#include <mma.h>
#include <math.h>

using namespace nvcuda;

#define NN 8192
#define ELLW 320
#define KP1 800   // K=784 padded to multiple of 32

// padded smem strides (bank-conflict-free LDSM)
#define LDA_S 40   // A tile row stride in bf16 (80B)
#define LDB_S 72   // B tile row stride in bf16 (144B)

// ---------------- scratch (device globals; no allocation allowed) ----------
__device__ float g_d[NN];
__device__ int   g_cnt[NN];
__device__ int   g_colidx[NN * ELLW];
__device__ float g_H0s[NN * 256];
__device__ float g_X1s[NN * 256];
__device__ float g_ZS[NN * 384];
__device__ float g_S1 [NN * 256];
__device__ float g_S1s[NN * 256];
__device__ float g_U [NN * 256];
__device__ float g_bcat [384];
__device__ float g_Wcat2[128 * 192];
__device__ float g_bcat2[192];
__device__ float g_xp1[256 * 128];
__device__ float g_A2 [256 * 256];
__device__ float g_T  [256 * 256];
__device__ float g_X2 [256 * 128];
__device__ float g_ZS2[256 * 192];
__device__ float g_S2 [256 * 64];
__device__ float g_V2 [256 * 64];
__device__ float g_xp2[64 * 128];
__device__ float g_A3 [64 * 64];
__device__ float g_X3 [64 * 128];
__device__ float g_Z3 [64 * 128];

// bf16 hi/lo split buffers
__device__ __align__(16) __nv_bfloat16 g_xhi[NN * KP1];
__device__ __align__(16) __nv_bfloat16 g_xlo[NN * KP1];
__device__ __align__(16) __nv_bfloat16 g_w1hi[KP1 * 256];
__device__ __align__(16) __nv_bfloat16 g_w1lo[KP1 * 256];
__device__ __align__(16) __nv_bfloat16 g_Yhi[NN * 256];
__device__ __align__(16) __nv_bfloat16 g_Ylo[NN * 256];
__device__ __align__(16) __nv_bfloat16 g_wchi[256 * 384];
__device__ __align__(16) __nv_bfloat16 g_wclo[256 * 384];

// ---------------- one-pass ELL build + degrees ------------------------------
__global__ void ell_build(const float* __restrict__ adj, int* __restrict__ colidx,
                          int* __restrict__ cnt, float* __restrict__ drs) {
    int row = blockIdx.x;
    int tid = threadIdx.x, lane = tid & 31, w = tid >> 5;
    const float* ar = adj + (size_t)row * NN;
    __shared__ int woff[9];
    int base = w * 1024;
    unsigned msk = 0;
#pragma unroll
    for (int s = 0; s < 32; s++) {
        float v = ar[base + s * 32 + lane];
        msk |= (v != 0.f) ? (1u << s) : 0u;
    }
    int c = __popc(msk);
    for (int o = 16; o > 0; o >>= 1) c += __shfl_down_sync(0xffffffffu, c, o);
    if (lane == 0) woff[w + 1] = c;
    __syncthreads();
    if (tid == 0) {
        woff[0] = 0;
        for (int i = 1; i <= 8; i++) woff[i] += woff[i - 1];
    }
    __syncthreads();
    int off = woff[w];
    unsigned ltmask = (1u << lane) - 1u;
    int* ci = colidx + (size_t)row * ELLW;
#pragma unroll
    for (int s = 0; s < 32; s++) {
        unsigned bit = (msk >> s) & 1u;
        unsigned m = __ballot_sync(0xffffffffu, bit);
        if (bit) {
            int pos = off + __popc(m & ltmask);
            if (pos < ELLW) ci[pos] = base + s * 32 + lane;
        }
        off += __popc(m);
    }
    if (tid == 0) {
        int tot = woff[8];
        cnt[row] = tot;
        drs[row] = rsqrtf((float)tot);
    }
}

// ---------------- bf16 split conversions ------------------------------------
__global__ void cvt_pad_cols(const float* __restrict__ in,
                             __nv_bfloat16* __restrict__ hi,
                             __nv_bfloat16* __restrict__ lo,
                             int M, int K, int KPp) {
    int idx = blockIdx.x * blockDim.x + threadIdx.x;
    if (idx >= M * KPp) return;
    int r = idx / KPp, c = idx - r * KPp;
    float v = (c < K) ? in[(size_t)r * K + c] : 0.f;
    __nv_bfloat16 h = __float2bfloat16(v);
    hi[idx] = h;
    lo[idx] = __float2bfloat16(v - __bfloat162float(h));
}

__global__ void cvt_pad_rows(const float* __restrict__ in,
                             __nv_bfloat16* __restrict__ hi,
                             __nv_bfloat16* __restrict__ lo,
                             int K, int KPp, int N) {
    int idx = blockIdx.x * blockDim.x + threadIdx.x;
    if (idx >= KPp * N) return;
    int r = idx / N;
    float v = (r < K) ? in[idx] : 0.f;
    __nv_bfloat16 h = __float2bfloat16(v);
    hi[idx] = h;
    lo[idx] = __float2bfloat16(v - __bfloat162float(h));
}

// pack [W_d11 | W_d12] and split to bf16 hi/lo in one pass; also bcat
__global__ void pack_wcat_split(const float* __restrict__ Wd11,
                                const float* __restrict__ Wd12,
                                const float* __restrict__ bd11,
                                const float* __restrict__ bd12,
                                __nv_bfloat16* __restrict__ hi,
                                __nv_bfloat16* __restrict__ lo,
                                float* __restrict__ bcat) {
    int idx = blockIdx.x * blockDim.x + threadIdx.x;
    if (idx < 256 * 384) {
        int k = idx / 384, n = idx % 384;
        float v = (n < 128) ? Wd11[k * 128 + n] : Wd12[k * 256 + (n - 128)];
        __nv_bfloat16 h = __float2bfloat16(v);
        hi[idx] = h;
        lo[idx] = __float2bfloat16(v - __bfloat162float(h));
    }
    if (idx < 384) bcat[idx] = (idx < 128) ? bd11[idx] : bd12[idx - 128];
}

// ---------------- tensor GEMM: 64x64 tile, padded smem, 2-stage cp.async ---
__device__ __forceinline__ void cp16(void* sp, const void* gp) {
    unsigned a = (unsigned)__cvta_generic_to_shared(sp);
    asm volatile("cp.async.cg.shared.global [%0], [%1], 16;\n" :: "r"(a), "l"(gp));
}

#define STG_STRIDE 19456

__global__ __launch_bounds__(128) void wgemm3(const __nv_bfloat16* __restrict__ Ahi,
                                              const __nv_bfloat16* __restrict__ Alo,
                                              const __nv_bfloat16* __restrict__ Bhi,
                                              const __nv_bfloat16* __restrict__ Blo,
                                              float* __restrict__ C,
                                              int M, int N, int KPk,
                                              const float* __restrict__ bias,
                                              const float* __restrict__ rowscale) {
    __shared__ __align__(16) char smem[2 * STG_STRIDE];
    int tid = threadIdx.x;
    int wid = tid >> 5, lane = tid & 31;
    int wm = wid & 1, wn = wid >> 1;
    int bm = blockIdx.y * 64, bn = blockIdx.x * 64;

    wmma::fragment<wmma::accumulator, 16, 16, 16, float> acc[2][2];
#pragma unroll
    for (int i = 0; i < 2; i++)
#pragma unroll
        for (int j = 0; j < 2; j++) wmma::fill_fragment(acc[i][j], 0.f);

    int a_r = tid >> 2, a_c = (tid & 3) * 8;
    int b_r = tid >> 3, b_c = (tid & 7) * 8;

    int nk = KPk >> 5;
    auto sAhi = [&](int s) { return (__nv_bfloat16*)(smem + s * STG_STRIDE); };
    auto sAlo = [&](int s) { return (__nv_bfloat16*)(smem + s * STG_STRIDE + 5120); };
    auto sBhi = [&](int s) { return (__nv_bfloat16*)(smem + s * STG_STRIDE + 10240); };
    auto sBlo = [&](int s) { return (__nv_bfloat16*)(smem + s * STG_STRIDE + 14848); };

    auto load_stage = [&](int s, int k0) {
        __nv_bfloat16* ah = sAhi(s); __nv_bfloat16* al = sAlo(s);
        __nv_bfloat16* bh = sBhi(s); __nv_bfloat16* bl = sBlo(s);
#pragma unroll
        for (int i = 0; i < 2; i++) {
            int r = a_r + i * 32;
            cp16(&ah[r * LDA_S + a_c], &Ahi[(size_t)(bm + r) * KPk + k0 + a_c]);
            cp16(&al[r * LDA_S + a_c], &Alo[(size_t)(bm + r) * KPk + k0 + a_c]);
        }
#pragma unroll
        for (int i = 0; i < 2; i++) {
            int r = b_r + i * 16;
            cp16(&bh[r * LDB_S + b_c], &Bhi[(size_t)(k0 + r) * N + bn + b_c]);
            cp16(&bl[r * LDB_S + b_c], &Blo[(size_t)(k0 + r) * N + bn + b_c]);
        }
        asm volatile("cp.async.commit_group;\n");
    };

    load_stage(0, 0);
    for (int it = 0; it < nk; it++) {
        if (it + 1 < nk) {
            load_stage((it + 1) & 1, (it + 1) * 32);
            asm volatile("cp.async.wait_group 1;\n");
        } else {
            asm volatile("cp.async.wait_group 0;\n");
        }
        __syncthreads();
        int s = it & 1;
        __nv_bfloat16* ah_ = sAhi(s); __nv_bfloat16* al_ = sAlo(s);
        __nv_bfloat16* bh_ = sBhi(s); __nv_bfloat16* bl_ = sBlo(s);
#pragma unroll
        for (int ks = 0; ks < 2; ks++) {
            wmma::fragment<wmma::matrix_b, 16, 16, 16, __nv_bfloat16, wmma::row_major> bh[2], bl[2];
#pragma unroll
            for (int j = 0; j < 2; j++) {
                wmma::load_matrix_sync(bh[j], bh_ + (ks * 16) * LDB_S + wn * 32 + j * 16, LDB_S);
                wmma::load_matrix_sync(bl[j], bl_ + (ks * 16) * LDB_S + wn * 32 + j * 16, LDB_S);
            }
#pragma unroll
            for (int i = 0; i < 2; i++) {
                wmma::fragment<wmma::matrix_a, 16, 16, 16, __nv_bfloat16, wmma::row_major> ah, al;
                wmma::load_matrix_sync(ah, ah_ + (wm * 32 + i * 16) * LDA_S + ks * 16, LDA_S);
                wmma::load_matrix_sync(al, al_ + (wm * 32 + i * 16) * LDA_S + ks * 16, LDA_S);
#pragma unroll
                for (int j = 0; j < 2; j++) {
                    wmma::mma_sync(acc[i][j], ah, bh[j], acc[i][j]);
                    wmma::mma_sync(acc[i][j], ah, bl[j], acc[i][j]);
                    wmma::mma_sync(acc[i][j], al, bh[j], acc[i][j]);
                }
            }
        }
        __syncthreads();
    }

    float* myout = (float*)smem + wid * (32 * 36);
#pragma unroll
    for (int i = 0; i < 2; i++)
#pragma unroll
        for (int j = 0; j < 2; j++)
            wmma::store_matrix_sync(myout + i * 16 * 36 + j * 16, acc[i][j], 36,
                                    wmma::mem_row_major);
    int colg = bn + wn * 32 + lane;
    float bb = bias ? bias[colg] : 0.f;
#pragma unroll 4
    for (int rr = 0; rr < 32; rr++) {
        int rowg = bm + wm * 32 + rr;
        float sc = rowscale ? rowscale[rowg] : 1.f;
        C[(size_t)rowg * N + colg] = sc * (myout[rr * 36 + lane] + bb);
    }
}

// ---------------- SpMM ------------------------------------------------------
__global__ __launch_bounds__(256) void spmm4(const int* __restrict__ colidx,
                                             const int* __restrict__ cnt,
                                             const float* __restrict__ drs,
                                             const float4* __restrict__ B,
                                             float4* __restrict__ out,
                                             const float4* __restrict__ bias,
                                             __nv_bfloat162* __restrict__ outhi,
                                             __nv_bfloat162* __restrict__ outlo,
                                             int mode) {
    __shared__ int sidx[ELLW];
    __shared__ float4 sred[192];
    int row = blockIdx.x;
    int tid = threadIdx.x;
    int g = tid >> 6, c = tid & 63;
    int e = cnt[row];
    if (e > ELLW) e = ELLW;
    for (int i = tid; i < e; i += 256) sidx[i] = colidx[(size_t)row * ELLW + i];
    __syncthreads();

    float4 acc = make_float4(0.f, 0.f, 0.f, 0.f);
    int p = g;
    for (; p + 8 <= e; p += 8) {
        int j0 = sidx[p], j1 = sidx[p + 4];
        float4 v0 = B[(size_t)j0 * 64 + c];
        float4 v1 = B[(size_t)j1 * 64 + c];
        acc.x += v0.x; acc.y += v0.y; acc.z += v0.z; acc.w += v0.w;
        acc.x += v1.x; acc.y += v1.y; acc.z += v1.z; acc.w += v1.w;
    }
    for (; p < e; p += 4) {
        int j = sidx[p];
        float4 v = B[(size_t)j * 64 + c];
        acc.x += v.x; acc.y += v.y; acc.z += v.z; acc.w += v.w;
    }
    if (g > 0) sred[(g - 1) * 64 + c] = acc;
    __syncthreads();
    if (g == 0) {
        float4 a1 = sred[c], a2 = sred[64 + c], a3 = sred[128 + c];
        acc.x += a1.x + a2.x + a3.x;
        acc.y += a1.y + a2.y + a3.y;
        acc.z += a1.z + a2.z + a3.z;
        acc.w += a1.w + a2.w + a3.w;
        float s = drs[row];
        float4 r;
        if (mode == 1) {
            float4 b = bias[c];
            r.x = s * (s * acc.x + b.x);
            r.y = s * (s * acc.y + b.y);
            r.z = s * (s * acc.z + b.z);
            r.w = s * (s * acc.w + b.w);
        } else {
            r.x = s * acc.x; r.y = s * acc.y; r.z = s * acc.z; r.w = s * acc.w;
        }
        if (mode == 2) {
            __nv_bfloat16 h0 = __float2bfloat16(r.x);
            __nv_bfloat16 h1 = __float2bfloat16(r.y);
            __nv_bfloat16 h2 = __float2bfloat16(r.z);
            __nv_bfloat16 h3 = __float2bfloat16(r.w);
            outhi[(size_t)row * 128 + 2 * c]     = __nv_bfloat162(h0, h1);
            outhi[(size_t)row * 128 + 2 * c + 1] = __nv_bfloat162(h2, h3);
            outlo[(size_t)row * 128 + 2 * c] = __nv_bfloat162(
                __float2bfloat16(r.x - __bfloat162float(h0)),
                __float2bfloat16(r.y - __bfloat162float(h1)));
            outlo[(size_t)row * 128 + 2 * c + 1] = __nv_bfloat162(
                __float2bfloat16(r.z - __bfloat162float(h2)),
                __float2bfloat16(r.w - __bfloat162float(h3)));
        } else {
            out[(size_t)row * 64 + c] = r;
        }
    }
}

// ---------------- softmaxes --------------------------------------------------
__global__ void softmax_dual(const float* __restrict__ in, int ldi, int off,
                             const float* __restrict__ drs,
                             float* __restrict__ out, float* __restrict__ outs) {
    int row = blockIdx.x, t = threadIdx.x;
    __shared__ float sm[8];
    float v = in[(size_t)row * ldi + off + t];
    float m = v;
    for (int o = 16; o > 0; o >>= 1) m = fmaxf(m, __shfl_xor_sync(0xffffffffu, m, o));
    if ((t & 31) == 0) sm[t >> 5] = m;
    __syncthreads();
    if (t < 8) {
        float mm = sm[t];
        for (int o = 4; o > 0; o >>= 1) mm = fmaxf(mm, __shfl_xor_sync(0xffu, mm, o));
        sm[t] = mm;
    }
    __syncthreads();
    float mx = sm[0];
    __syncthreads();
    float e = expf(v - mx);
    float s = e;
    for (int o = 16; o > 0; o >>= 1) s += __shfl_xor_sync(0xffffffffu, s, o);
    if ((t & 31) == 0) sm[t >> 5] = s;
    __syncthreads();
    if (t < 8) {
        float ss = sm[t];
        for (int o = 4; o > 0; o >>= 1) ss += __shfl_xor_sync(0xffu, ss, o);
        sm[t] = ss;
    }
    __syncthreads();
    float r = e / sm[0];
    out[(size_t)row * 256 + t] = r;
    outs[(size_t)row * 256 + t] = drs[row] * r;
}

__global__ void softmax_small(const float* __restrict__ in, int ldi, int off,
                              float* __restrict__ out, int ldo) {
    int row = blockIdx.x, t = threadIdx.x;
    __shared__ float sm[2];
    float v = in[(size_t)row * ldi + off + t];
    float m = v;
    for (int o = 16; o > 0; o >>= 1) m = fmaxf(m, __shfl_xor_sync(0xffffffffu, m, o));
    if ((t & 31) == 0) sm[t >> 5] = m;
    __syncthreads();
    float mx = fmaxf(sm[0], sm[1]);
    float e = expf(v - mx);
    float s = e;
    for (int o = 16; o > 0; o >>= 1) s += __shfl_xor_sync(0xffffffffu, s, o);
    if ((t & 31) == 0) sm[t >> 5] = s;
    __syncthreads();
    out[(size_t)row * ldo + t] = e / (sm[0] + sm[1]);
}

// ---------------- transpose GEMM: C += S^T @ V (16 rows/block, R8 config) ---
__global__ void tgemm_kernel(const float* __restrict__ S, int lds,
                             const float* __restrict__ V, int ldv,
                             float* __restrict__ C, int ldc, int K) {
    int ag = blockIdx.x * 16;
    int kchunk = K / gridDim.y;
    int k0 = blockIdx.y * kchunk, k1 = k0 + kchunk;
    int t = threadIdx.x;
    float acc[16];
#pragma unroll
    for (int u = 0; u < 16; u++) acc[u] = 0.f;
#pragma unroll 2
    for (int k = k0; k < k1; k++) {
        float v = V[(size_t)k * ldv + t];
        const float4* sp = (const float4*)(S + (size_t)k * lds + ag);
        float4 s0 = sp[0], s1 = sp[1], s2 = sp[2], s3 = sp[3];
        acc[0] += s0.x * v; acc[1] += s0.y * v; acc[2] += s0.z * v; acc[3] += s0.w * v;
        acc[4] += s1.x * v; acc[5] += s1.y * v; acc[6] += s1.z * v; acc[7] += s1.w * v;
        acc[8] += s2.x * v; acc[9] += s2.y * v; acc[10] += s2.z * v; acc[11] += s2.w * v;
        acc[12] += s3.x * v; acc[13] += s3.y * v; acc[14] += s3.z * v; acc[15] += s3.w * v;
    }
#pragma unroll
    for (int u = 0; u < 16; u++) atomicAdd(&C[(ag + u) * ldc + t], acc[u]);
}

__global__ void zero2_kernel(float* a, int na, float* b, int nb) {
    int i = blockIdx.x * blockDim.x + threadIdx.x;
    if (i < na) a[i] = 0.f;
    else if (i < na + nb) b[i - na] = 0.f;
}

// ---------------- small dense GEMMs -----------------------------------------
__global__ void gemm_small(const float* __restrict__ A, int lda,
                           const float* __restrict__ B, int ldb,
                           float* __restrict__ C, int ldc, int K,
                           const float* __restrict__ bias) {
    int m = blockIdx.x, t = threadIdx.x;
    const float* a = A + (size_t)m * lda;
    float acc = 0.f;
#pragma unroll 8
    for (int k = 0; k < K; k++) acc += a[k] * B[(size_t)k * ldb + t];
    if (bias) acc += bias[t];
    C[(size_t)m * ldc + t] = acc;
}

__global__ void gemm_small_AT(const float* __restrict__ A, int lda,
                              const float* __restrict__ B, int ldb,
                              float* __restrict__ C, int ldc, int K) {
    int m = blockIdx.x, t = threadIdx.x;
    float acc = 0.f;
#pragma unroll 8
    for (int k = 0; k < K; k++) acc += A[(size_t)k * lda + m] * B[(size_t)k * ldb + t];
    C[(size_t)m * ldc + t] = acc;
}

// ---------------- pack [W_d21 | W_d22] ---------------------------------------
__global__ void pack_wcat2(const float* __restrict__ Wd21, const float* __restrict__ Wd22,
                           const float* __restrict__ bd21, const float* __restrict__ bd22,
                           float* __restrict__ Wcat, float* __restrict__ bcat) {
    int idx = blockIdx.x * blockDim.x + threadIdx.x;
    if (idx < 128 * 192) {
        int k = idx / 192, n = idx % 192;
        Wcat[idx] = (n < 128) ? Wd21[k * 128 + n] : Wd22[k * 64 + (n - 128)];
    }
    if (idx < 192) bcat[idx] = (idx < 128) ? bd21[idx] : bd22[idx - 128];
}

// ---------------- final ------------------------------------------------------
__global__ void final_kernel(const float* __restrict__ Z3, const float* __restrict__ Wfc,
                             const float* __restrict__ bfc, float* __restrict__ out) {
    __shared__ float xf[128];
    __shared__ float logits[10];
    __shared__ float red;
    int t = threadIdx.x;
    float s = 0.f;
    for (int r = 0; r < 64; r++) s += Z3[r * 128 + t];
    xf[t] = s;
    __syncthreads();
    if (t < 10) {
        float a = bfc[t];
        for (int k = 0; k < 128; k++) a += xf[k] * Wfc[k * 10 + t];
        logits[t] = a;
    }
    __syncthreads();
    if (t == 0) {
        float mx = logits[0];
        for (int i = 1; i < 10; i++) mx = fmaxf(mx, logits[i]);
        float se = 0.f;
        for (int i = 0; i < 10; i++) se += expf(logits[i] - mx);
        red = mx + logf(se);
    }
    __syncthreads();
    if (t < 10) out[t] = logits[t] - red;
}

// ---------------------------------------------------------------------------
static void* sym(const void* s) {
    void* p = nullptr;
    cudaGetSymbolAddress(&p, s);
    return p;
}

extern "C" void kernel_launch(void* const* d_in, const int* in_sizes, int n_in,
                              void* d_out, int out_size) {
    const float* x      = (const float*)d_in[0];
    const float* adj    = (const float*)d_in[1];
    const float* W_gcn1 = (const float*)d_in[2];
    const float* b_gcn1 = (const float*)d_in[3];
    const float* W_d11  = (const float*)d_in[4];
    const float* b_d11  = (const float*)d_in[5];
    const float* W_d12  = (const float*)d_in[6];
    const float* b_d12  = (const float*)d_in[7];
    const float* W_gcn2 = (const float*)d_in[8];
    const float* b_gcn2 = (const float*)d_in[9];
    const float* W_d21  = (const float*)d_in[10];
    const float* b_d21  = (const float*)d_in[11];
    const float* W_d22  = (const float*)d_in[12];
    const float* b_d22  = (const float*)d_in[13];
    const float* W_gcn3 = (const float*)d_in[14];
    const float* b_gcn3 = (const float*)d_in[15];
    const float* W_d31  = (const float*)d_in[16];
    const float* b_d31  = (const float*)d_in[17];
    // d_in[18]=W_d32, d_in[19]=b_d32: softmax over width-1 axis == 1 exactly -> unused
    const float* W_fc   = (const float*)d_in[20];
    const float* b_fc   = (const float*)d_in[21];
    float* out = (float*)d_out;

    float* dD    = (float*)sym(g_d);
    int*   dCnt  = (int*)sym(g_cnt);
    int*   dCi   = (int*)sym(g_colidx);
    float* H0s   = (float*)sym(g_H0s);
    float* X1s   = (float*)sym(g_X1s);
    float* ZS    = (float*)sym(g_ZS);
    float* S1    = (float*)sym(g_S1);
    float* S1s   = (float*)sym(g_S1s);
    float* U     = (float*)sym(g_U);
    float* bcat  = (float*)sym(g_bcat);
    float* Wcat2 = (float*)sym(g_Wcat2);
    float* bcat2 = (float*)sym(g_bcat2);
    float* xp1   = (float*)sym(g_xp1);
    float* A2    = (float*)sym(g_A2);
    float* T     = (float*)sym(g_T);
    float* X2    = (float*)sym(g_X2);
    float* ZS2   = (float*)sym(g_ZS2);
    float* S2    = (float*)sym(g_S2);
    float* V2    = (float*)sym(g_V2);
    float* xp2   = (float*)sym(g_xp2);
    float* A3    = (float*)sym(g_A3);
    float* X3    = (float*)sym(g_X3);
    float* Z3    = (float*)sym(g_Z3);
    __nv_bfloat16* xhi  = (__nv_bfloat16*)sym(g_xhi);
    __nv_bfloat16* xlo  = (__nv_bfloat16*)sym(g_xlo);
    __nv_bfloat16* w1hi = (__nv_bfloat16*)sym(g_w1hi);
    __nv_bfloat16* w1lo = (__nv_bfloat16*)sym(g_w1lo);
    __nv_bfloat16* Yhi  = (__nv_bfloat16*)sym(g_Yhi);
    __nv_bfloat16* Ylo  = (__nv_bfloat16*)sym(g_Ylo);
    __nv_bfloat16* wchi = (__nv_bfloat16*)sym(g_wchi);
    __nv_bfloat16* wclo = (__nv_bfloat16*)sym(g_wclo);

    // ---- ELL build + degree factors (one adjacency pass) ----
    ell_build<<<NN, 256>>>(adj, dCi, dCnt, dD);

    // ---- bf16 hi/lo splits (K padded 784 -> 800) ----
    cvt_pad_cols<<<(NN * KP1 + 255) / 256, 256>>>(x, xhi, xlo, NN, 784, KP1);
    cvt_pad_rows<<<(KP1 * 256 + 255) / 256, 256>>>(W_gcn1, w1hi, w1lo, 784, KP1, 256);

    // ---- level 1 ----
    wgemm3<<<dim3(256 / 64, NN / 64), 128>>>(xhi, xlo, w1hi, w1lo, H0s,
                                             NN, 256, KP1, nullptr, dD);
    spmm4<<<NN, 256>>>(dCi, dCnt, dD, (const float4*)H0s, (float4*)X1s,
                       (const float4*)b_gcn1, nullptr, nullptr, 1);
    spmm4<<<NN, 256>>>(dCi, dCnt, dD, (const float4*)X1s, nullptr, nullptr,
                       (__nv_bfloat162*)Yhi, (__nv_bfloat162*)Ylo, 2);

    pack_wcat_split<<<(256 * 384 + 255) / 256, 256>>>(W_d11, W_d12, b_d11, b_d12,
                                                      wchi, wclo, bcat);
    wgemm3<<<dim3(384 / 64, NN / 64), 128>>>(Yhi, Ylo, wchi, wclo, ZS,
                                             NN, 384, 256, bcat, nullptr);

    softmax_dual<<<NN, 256>>>(ZS, 384, 128, dD, S1, S1s);
    spmm4<<<NN, 256>>>(dCi, dCnt, dD, (const float4*)S1s, (float4*)U,
                       nullptr, nullptr, nullptr, 0);

    zero2_kernel<<<(256 * 128 + 256 * 256 + 255) / 256, 256>>>(xp1, 256 * 128, A2, 256 * 256);
    tgemm_kernel<<<dim3(16, 32), 128>>>(S1, 256, ZS, 384, xp1, 128, NN);  // s1^T @ z1
    tgemm_kernel<<<dim3(16, 32), 256>>>(S1, 256, U, 256, A2, 256, NN);    // s1^T @ U

    // ---- level 2 (256 nodes) ----
    pack_wcat2<<<(128 * 192 + 255) / 256, 256>>>(W_d21, W_d22, b_d21, b_d22, Wcat2, bcat2);
    gemm_small<<<256, 128>>>(xp1, 128, W_gcn2, 128, T, 128, 128, nullptr);
    gemm_small<<<256, 128>>>(A2, 256, T, 128, X2, 128, 256, b_gcn2);
    gemm_small<<<256, 192>>>(X2, 128, Wcat2, 192, T, 192, 128, nullptr);
    gemm_small<<<256, 192>>>(A2, 256, T, 192, ZS2, 192, 256, bcat2);
    softmax_small<<<256, 64>>>(ZS2, 192, 128, S2, 64);
    gemm_small_AT<<<64, 128>>>(S2, 64, ZS2, 192, xp2, 128, 256);
    gemm_small<<<256, 64>>>(A2, 256, S2, 64, V2, 64, 256, nullptr);
    gemm_small_AT<<<64, 64>>>(S2, 64, V2, 64, A3, 64, 256);

    // ---- level 3 (64 nodes) ----
    gemm_small<<<64, 128>>>(xp2, 128, W_gcn3, 128, T, 128, 128, nullptr);
    gemm_small<<<64, 128>>>(A3, 64, T, 128, X3, 128, 64, b_gcn3);
    gemm_small<<<64, 128>>>(X3, 128, W_d31, 128, T, 128, 128, nullptr);
    gemm_small<<<64, 128>>>(A3, 64, T, 128, Z3, 128, 64, b_d31);

    // s3 == ones -> final = colsum(Z3) @ W_fc + b_fc -> log_softmax
    final_kernel<<<1, 128>>>(Z3, W_fc, b_fc, out);
}